// round 1
// baseline (speedup 1.0000x reference)
#include <cuda_runtime.h>
#include <math_constants.h>

// Problem constants (fixed shapes per reference setup_inputs)
#define BATCH   8
#define NPTS    8192
#define EPSF    1e-12f

#define THREADS 128
#define PREG    4                      // x-points per thread (register blocked)
#define PTSBLK  (THREADS * PREG)       // 512 x-points per block
#define CHUNKS  (NPTS / PTSBLK)        // 16 chunks per (dir,batch)
#define NBLOCKS (2 * BATCH * CHUNKS)   // 256 blocks
#define TILEY   1024                   // y-points per smem tile (16KB)

// Scratch (no cudaMalloc allowed): packed y records and global accumulator.
// g_pack[s][b*NPTS + j] = (-2*y.x, -2*y.y, -2*y.z, |y|^2) for input s.
__device__ float4 g_pack[2][BATCH * NPTS];
__device__ float  g_acc;

__global__ void zero_kernel() { g_acc = 0.0f; }

__global__ void pack_kernel(const float* __restrict__ xyz1,
                            const float* __restrict__ xyz2) {
    int idx = blockIdx.x * blockDim.x + threadIdx.x;   // 0 .. BATCH*NPTS-1
    if (idx >= BATCH * NPTS) return;
    const float* src = (blockIdx.y == 0) ? xyz1 : xyz2;
    float x = src[idx * 3 + 0];
    float y = src[idx * 3 + 1];
    float z = src[idx * 3 + 2];
    g_pack[blockIdx.y][idx] =
        make_float4(-2.0f * x, -2.0f * y, -2.0f * z, x * x + y * y + z * z);
}

// One block: PTSBLK x-points of one (direction, batch) slice.
// candidate c_j = |y_j|^2 - 2 x·y_j  (3 FFMA via packed y record),
// d_i = |x_i|^2 + min_j c_j ; dist = sqrt(max(d, EPS)); sum everything.
__global__ void __launch_bounds__(THREADS)
chamfer_kernel(const float* __restrict__ xyz1,
               const float* __restrict__ xyz2) {
    __shared__ float4 sh[TILEY];
    __shared__ float  wsum[THREADS / 32];

    const int bx    = blockIdx.x;
    const int dir   = bx >> 7;          // 0: x from xyz1 vs pack(xyz2); 1: swapped
    const int batch = (bx >> 4) & (BATCH - 1);
    const int chunk = bx & (CHUNKS - 1);

    const float*  X = ((dir == 0) ? xyz1 : xyz2) + (size_t)batch * NPTS * 3;
    const float4* Y = g_pack[dir ^ 1] + batch * NPTS;

    float xx[PREG], xy[PREG], xz[PREG], n1[PREG], mn[PREG];
    const int base = chunk * PTSBLK + threadIdx.x;
#pragma unroll
    for (int p = 0; p < PREG; p++) {
        int i = base + p * THREADS;
        xx[p] = X[i * 3 + 0];
        xy[p] = X[i * 3 + 1];
        xz[p] = X[i * 3 + 2];
        n1[p] = xx[p] * xx[p] + xy[p] * xy[p] + xz[p] * xz[p];
        mn[p] = CUDART_INF_F;
    }

    for (int t = 0; t < NPTS; t += TILEY) {
        __syncthreads();   // previous tile fully consumed
#pragma unroll
        for (int j = threadIdx.x; j < TILEY; j += THREADS)
            sh[j] = Y[t + j];
        __syncthreads();

#pragma unroll 4
        for (int j = 0; j < TILEY; j++) {
            float4 y4 = sh[j];   // LDS.128 broadcast (all lanes same addr)
#pragma unroll
            for (int p = 0; p < PREG; p++) {
                float c = fmaf(xz[p], y4.z, y4.w);
                c = fmaf(xy[p], y4.y, c);
                c = fmaf(xx[p], y4.x, c);
                mn[p] = fminf(mn[p], c);
            }
        }
    }

    // per-thread sum of sqrt distances
    float s = 0.0f;
#pragma unroll
    for (int p = 0; p < PREG; p++)
        s += sqrtf(fmaxf(n1[p] + mn[p], EPSF));

    // warp reduce
#pragma unroll
    for (int o = 16; o > 0; o >>= 1)
        s += __shfl_down_sync(0xFFFFFFFFu, s, o);
    if ((threadIdx.x & 31) == 0) wsum[threadIdx.x >> 5] = s;
    __syncthreads();
    if (threadIdx.x == 0) {
        float b = 0.0f;
#pragma unroll
        for (int w = 0; w < THREADS / 32; w++) b += wsum[w];
        atomicAdd(&g_acc, b);
    }
}

// mean_b[(mean_i dist1 + mean_j dist2)/2] == total_sum / (2*B*N)
__global__ void final_kernel(float* __restrict__ out) {
    out[0] = g_acc * (1.0f / (2.0f * BATCH * NPTS));
}

extern "C" void kernel_launch(void* const* d_in, const int* in_sizes, int n_in,
                              void* d_out, int out_size) {
    const float* xyz1 = (const float*)d_in[0];
    const float* xyz2 = (const float*)d_in[1];
    float* out = (float*)d_out;

    zero_kernel<<<1, 1>>>();
    pack_kernel<<<dim3((BATCH * NPTS + 255) / 256, 2), 256>>>(xyz1, xyz2);
    chamfer_kernel<<<NBLOCKS, THREADS>>>(xyz1, xyz2);
    final_kernel<<<1, 1>>>(out);
}

// round 2
// speedup vs baseline: 1.0945x; 1.0945x over previous
#include <cuda_runtime.h>
#include <math_constants.h>
#include <cstdint>

// Fixed shapes per reference setup_inputs
#define BATCH   8
#define NPTS    8192
#define EPSF    1e-12f

#define THREADS 128
#define PREG    4                         // x-points per thread (2 packed f32x2 chains)
#define PTSBLK  (THREADS * PREG)          // 512 x-points per block
#define XCHUNKS (NPTS / PTSBLK)           // 16
#define YSPLIT  4
#define YRANGE  (NPTS / YSPLIT)           // 2048 y per block
#define TILEY   512                       // y per smem tile (16KB duplicated)
#define NBLOCKS (2 * BATCH * XCHUNKS * YSPLIT)  // 1024

// Scratch (no cudaMalloc allowed).
// g_pack[s][b*NPTS+j] = (-2yx, -2yy, -2yz, |y|^2)
__device__ float4 g_pack[2][BATCH * NPTS];
// partial mins of c_j = |y|^2 - 2 x.y over each y-split
__device__ float  g_pmin[YSPLIT][2 * BATCH * NPTS];

// ---- f32x2 helpers (Blackwell packed fp32) ----
__device__ __forceinline__ uint64_t pk2(float lo, float hi) {
    uint64_t r;
    asm("mov.b64 %0, {%1, %2};" : "=l"(r) : "f"(lo), "f"(hi));
    return r;
}
__device__ __forceinline__ void upk2(uint64_t v, float& lo, float& hi) {
    asm("mov.b64 {%0, %1}, %2;" : "=f"(lo), "=f"(hi) : "l"(v));
}
__device__ __forceinline__ uint64_t fma2(uint64_t a, uint64_t b, uint64_t c) {
    uint64_t d;
    asm("fma.rn.f32x2 %0, %1, %2, %3;" : "=l"(d) : "l"(a), "l"(b), "l"(c));
    return d;
}

// Pack y records; also zero the output accumulator (d_out).
__global__ void pack_kernel(const float* __restrict__ xyz1,
                            const float* __restrict__ xyz2,
                            float* __restrict__ out) {
    int idx = blockIdx.x * blockDim.x + threadIdx.x;
    if (idx == 0 && blockIdx.y == 0) out[0] = 0.0f;
    if (idx >= BATCH * NPTS) return;
    const float* src = (blockIdx.y == 0) ? xyz1 : xyz2;
    float x = src[idx * 3 + 0];
    float y = src[idx * 3 + 1];
    float z = src[idx * 3 + 2];
    g_pack[blockIdx.y][idx] =
        make_float4(-2.0f * x, -2.0f * y, -2.0f * z, x * x + y * y + z * z);
}

// One block: 512 x-points vs one y-split (2048 y) of one (dir,batch).
__global__ void __launch_bounds__(THREADS)
partial_kernel(const float* __restrict__ xyz1,
               const float* __restrict__ xyz2) {
    __shared__ float4 sh[TILEY * 2];   // duplicated: (x,x,y,y) (z,z,w,w) per y

    const int bx    = blockIdx.x;
    const int dir   = bx & 1;
    const int batch = (bx >> 1) & (BATCH - 1);
    const int chunk = (bx >> 4) & (XCHUNKS - 1);
    const int ys    = bx >> 8;

    const float*  X = ((dir == 0) ? xyz1 : xyz2) + (size_t)batch * NPTS * 3;
    const float4* Y = g_pack[dir ^ 1] + batch * NPTS + ys * YRANGE;
    float* out = g_pmin[ys] + (size_t)dir * BATCH * NPTS + batch * NPTS
               + chunk * PTSBLK;

    // Load PREG x-points, pack into f32x2 operands.
    float xx[PREG], xy[PREG], xz[PREG];
    const int base = chunk * PTSBLK + threadIdx.x;
#pragma unroll
    for (int p = 0; p < PREG; p++) {
        int i = base + p * THREADS;
        xx[p] = X[i * 3 + 0];
        xy[p] = X[i * 3 + 1];
        xz[p] = X[i * 3 + 2];
    }
    const uint64_t PX0 = pk2(xx[0], xx[1]), PX1 = pk2(xx[2], xx[3]);
    const uint64_t PY0 = pk2(xy[0], xy[1]), PY1 = pk2(xy[2], xy[3]);
    const uint64_t PZ0 = pk2(xz[0], xz[1]), PZ1 = pk2(xz[2], xz[3]);

    float mn0 = CUDART_INF_F, mn1 = CUDART_INF_F;
    float mn2 = CUDART_INF_F, mn3 = CUDART_INF_F;

    for (int t = 0; t < YRANGE; t += TILEY) {
        __syncthreads();
#pragma unroll
        for (int j = threadIdx.x; j < TILEY; j += THREADS) {
            float4 v = Y[t + j];
            sh[2 * j + 0] = make_float4(v.x, v.x, v.y, v.y);
            sh[2 * j + 1] = make_float4(v.z, v.z, v.w, v.w);
        }
        __syncthreads();

#pragma unroll 4
        for (int j = 0; j < TILEY; j++) {
            // Two LDS.128 (broadcast): packed (-2yx,-2yx),(-2yy,-2yy),(-2yz,-2yz),(n2,n2)
            const ulonglong2* pa = (const ulonglong2*)&sh[2 * j];
            ulonglong2 A = pa[0];
            ulonglong2 B = pa[1];
            uint64_t c0 = fma2(PZ0, B.x, B.y);
            uint64_t c1 = fma2(PZ1, B.x, B.y);
            c0 = fma2(PY0, A.y, c0);
            c1 = fma2(PY1, A.y, c1);
            c0 = fma2(PX0, A.x, c0);
            c1 = fma2(PX1, A.x, c1);
            float f0, f1, f2, f3;
            upk2(c0, f0, f1);
            upk2(c1, f2, f3);
            mn0 = fminf(mn0, f0);
            mn1 = fminf(mn1, f1);
            mn2 = fminf(mn2, f2);
            mn3 = fminf(mn3, f3);
        }
    }

    out[threadIdx.x + 0 * THREADS] = mn0;
    out[threadIdx.x + 1 * THREADS] = mn1;
    out[threadIdx.x + 2 * THREADS] = mn2;
    out[threadIdx.x + 3 * THREADS] = mn3;
}

// Combine y-split partial mins, add |x|^2, sqrt, global mean -> d_out.
__global__ void reduce_kernel(const float* __restrict__ xyz1,
                              const float* __restrict__ xyz2,
                              float* __restrict__ out) {
    __shared__ float wsum[8];
    int idx = blockIdx.x * 256 + threadIdx.x;       // 0 .. 2*B*N-1
    int dir = idx / (BATCH * NPTS);
    int r   = idx - dir * (BATCH * NPTS);
    const float* X = (dir == 0) ? xyz1 : xyz2;
    float a = X[r * 3 + 0], b = X[r * 3 + 1], c = X[r * 3 + 2];
    float n1 = a * a + b * b + c * c;

    float m = g_pmin[0][idx];
#pragma unroll
    for (int s = 1; s < YSPLIT; s++) m = fminf(m, g_pmin[s][idx]);

    float v = sqrtf(fmaxf(n1 + m, EPSF));

#pragma unroll
    for (int o = 16; o > 0; o >>= 1)
        v += __shfl_down_sync(0xFFFFFFFFu, v, o);
    if ((threadIdx.x & 31) == 0) wsum[threadIdx.x >> 5] = v;
    __syncthreads();
    if (threadIdx.x == 0) {
        float s = 0.0f;
#pragma unroll
        for (int w = 0; w < 8; w++) s += wsum[w];
        atomicAdd(out, s * (1.0f / (2.0f * BATCH * NPTS)));
    }
}

extern "C" void kernel_launch(void* const* d_in, const int* in_sizes, int n_in,
                              void* d_out, int out_size) {
    const float* xyz1 = (const float*)d_in[0];
    const float* xyz2 = (const float*)d_in[1];
    float* out = (float*)d_out;

    pack_kernel<<<dim3((BATCH * NPTS + 255) / 256, 2), 256>>>(xyz1, xyz2, out);
    partial_kernel<<<NBLOCKS, THREADS>>>(xyz1, xyz2);
    reduce_kernel<<<(2 * BATCH * NPTS) / 256, 256>>>(xyz1, xyz2, out);
}